// round 2
// baseline (speedup 1.0000x reference)
#include <cuda_runtime.h>
#include <cuda_bf16.h>
#include <stdint.h>

#define GN 512
#define GW 332
#define GH 324
#define GHW (GW * GH)
#define GC 120
#define TS 16

__device__ float g_gx[GN], g_gy[GN], g_c00[GN], g_c11[GN], g_op[GN], g_dep[GN];
__device__ int   g_sid[GN];
__device__ int   g_cnt;

static __device__ __forceinline__ unsigned order_float(float f) {
    unsigned u = __float_as_uint(f);
    return (u & 0x80000000u) ? ~u : (u | 0x80000000u);
}

// ---------------------------------------------------------------------------
// Kernel 1: project, validity, cinv, stable sort by depth, compact valid set.
// One block, 512 threads (one per gaussian).
// ---------------------------------------------------------------------------
__global__ __launch_bounds__(GN) void prep_kernel(
    const float* __restrict__ pos,     // [N,3]
    const float* __restrict__ scales,  // [N,3]
    const float* __restrict__ ops,     // [N]
    const float* __restrict__ K,       // [3,3]
    const float* __restrict__ E)       // [4,4]
{
    __shared__ float s_gx[GN], s_gy[GN], s_c00[GN], s_c11[GN], s_op[GN], s_dep[GN];
    __shared__ unsigned char s_valid[GN];
    __shared__ unsigned long long s_key[GN];
    __shared__ int s_wcnt[16];

    const int i = threadIdx.x;

    float p0 = pos[3 * i + 0], p1 = pos[3 * i + 1], p2 = pos[3 * i + 2];
    // cam = E @ [p;1]
    float cx = E[0] * p0 + E[1] * p1 + E[2]  * p2 + E[3];
    float cy = E[4] * p0 + E[5] * p1 + E[6]  * p2 + E[7];
    float cz = E[8] * p0 + E[9] * p1 + E[10] * p2 + E[11];
    // proj = K @ cam3
    float prx = K[0] * cx + K[1] * cy + K[2] * cz;
    float pry = K[3] * cx + K[4] * cy + K[5] * cz;
    float prz = K[6] * cx + K[7] * cy + K[8] * cz;
    float sx = prx / (prz + 1e-6f);
    float sy = pry / (prz + 1e-6f);
    float d  = cz;

    bool valid = (d > 0.01f) && (d < 100.0f) &&
                 (sx > -100.0f) && (sx < (float)GW + 100.0f) &&
                 (sy > -100.0f) && (sy < (float)GH + 100.0f);

    float s0 = scales[3 * i + 0], s1 = scales[3 * i + 1];
    s_gx[i]  = sx;
    s_gy[i]  = sy;
    s_c00[i] = 1.0f / (s0 * s0 + 1e-4f);
    s_c11[i] = 1.0f / (s1 * s1 + 1e-4f);
    s_op[i]  = ops[i];
    s_dep[i] = d;
    s_valid[i] = valid ? 1 : 0;
    s_key[i] = ((unsigned long long)order_float(d) << 32) | (unsigned)i;
    __syncthreads();

    // Bitonic sort 512 keys ascending (depth, then index => stable argsort).
    for (int k = 2; k <= GN; k <<= 1) {
        for (int j = k >> 1; j > 0; j >>= 1) {
            __syncthreads();
            int ixj = i ^ j;
            if (ixj > i) {
                unsigned long long a = s_key[i], b = s_key[ixj];
                bool asc = ((i & k) == 0);
                if ((a > b) == asc) { s_key[i] = b; s_key[ixj] = a; }
            }
        }
    }
    __syncthreads();

    // Order-preserving compaction of valid entries.
    int src = (int)(s_key[i] & 0xffffffffu);
    bool keep = (s_valid[src] != 0);
    unsigned bm = __ballot_sync(0xffffffffu, keep);
    int lane = i & 31, w = i >> 5;
    if (lane == 0) s_wcnt[w] = __popc(bm);
    __syncthreads();
    int woff = 0;
#pragma unroll
    for (int ww = 0; ww < 16; ww++)
        if (ww < w) woff += s_wcnt[ww];
    if (keep) {
        int p = woff + __popc(bm & ((1u << lane) - 1u));
        g_gx[p]  = s_gx[src];
        g_gy[p]  = s_gy[src];
        g_c00[p] = s_c00[src];
        g_c11[p] = s_c11[src];
        g_op[p]  = s_op[src];
        g_dep[p] = s_dep[src];
        g_sid[p] = src;
    }
    if (i == 0) {
        int tot = 0;
#pragma unroll
        for (int ww = 0; ww < 16; ww++) tot += s_wcnt[ww];
        g_cnt = tot;
    }
}

// ---------------------------------------------------------------------------
// Kernel 2: per-tile cull + per-pixel depth-ordered alpha compositing.
// Block = 256 threads = one 16x16 pixel tile. Grid = 21 x 21.
// ---------------------------------------------------------------------------
__global__ __launch_bounds__(256) void render_kernel(
    const float* __restrict__ spec,   // [N, C]
    const float* __restrict__ tone,   // [C]
    float* __restrict__ out)          // [C*HW + HW + HW]
{
    __shared__ float t_gx[GN], t_gy[GN], t_c00[GN], t_c11[GN], t_op[GN], t_d[GN];
    __shared__ int   t_id[GN];
    __shared__ float s_tone[GC];
    __shared__ int   s_cnt, s_wcnt[8];

    const int tid = threadIdx.x;
    if (tid < GC) s_tone[tid] = tone[tid];
    if (tid == 0) s_cnt = 0;

    const int M  = g_cnt;
    const int x0 = blockIdx.x * TS, y0 = blockIdx.y * TS;
    const float fx0 = (float)x0, fx1 = (float)(x0 + TS - 1);
    const float fy0 = (float)y0, fy1 = (float)(y0 + TS - 1);
    const float CUT = 36.0f;   // 6-sigma: exp(-18) ~ 1.5e-8
    __syncthreads();

    // Order-preserving tile cull (chunks of 256).
    for (int base = 0; base < M; base += 256) {
        int i = base + tid;
        bool keep = false;
        float gx = 0.f, gy = 0.f, c00 = 1.f, c11 = 1.f;
        if (i < M) {
            gx = g_gx[i]; gy = g_gy[i]; c00 = g_c00[i]; c11 = g_c11[i];
            float rx = sqrtf(CUT / c00);
            float ry = sqrtf(CUT / c11);
            keep = (gx + rx >= fx0) && (gx - rx <= fx1) &&
                   (gy + ry >= fy0) && (gy - ry <= fy1);
        }
        unsigned bm = __ballot_sync(0xffffffffu, keep);
        int lane = tid & 31, w = tid >> 5;
        if (lane == 0) s_wcnt[w] = __popc(bm);
        __syncthreads();
        int woff = 0;
#pragma unroll
        for (int ww = 0; ww < 8; ww++)
            if (ww < w) woff += s_wcnt[ww];
        if (keep) {
            int p = s_cnt + woff + __popc(bm & ((1u << lane) - 1u));
            t_gx[p] = gx; t_gy[p] = gy; t_c00[p] = c00; t_c11[p] = c11;
            t_op[p] = g_op[i]; t_d[p] = g_dep[i]; t_id[p] = g_sid[i];
        }
        __syncthreads();
        if (tid == 0) {
            int tt = 0;
#pragma unroll
            for (int ww = 0; ww < 8; ww++) tt += s_wcnt[ww];
            s_cnt += tt;
        }
        __syncthreads();
    }
    const int cnt = s_cnt;

    const int px = x0 + (tid & 15);
    const int py = y0 + (tid >> 4);
    const float fpx = (float)px, fpy = (float)py;

    float A = 0.0f, D = 0.0f;
    float acc[GC];
#pragma unroll
    for (int c = 0; c < GC; c++) acc[c] = 0.0f;

    // Depth-ordered compositing over culled list (uniform LDS broadcasts).
    for (int k = 0; k < cnt; k++) {
        float dx = fpx - t_gx[k];
        float dy = fpy - t_gy[k];
        float m  = dx * dx * t_c00[k] + dy * dy * t_c11[k];
        float alpha = 0.0f;
        if (m < CUT) alpha = t_op[k] * __expf(-0.5f * m) * (1.0f - A);
        if (__any_sync(0xffffffffu, alpha != 0.0f)) {
            A += alpha;
            D += t_d[k] * alpha;
            const float4* sp = (const float4*)(spec + (size_t)t_id[k] * GC);
#pragma unroll
            for (int q = 0; q < GC / 4; q++) {
                float4 v = __ldg(sp + q);
                acc[4 * q + 0] += alpha * v.x;
                acc[4 * q + 1] += alpha * v.y;
                acc[4 * q + 2] += alpha * v.z;
                acc[4 * q + 3] += alpha * v.w;
            }
        }
    }

    if (px < GW && py < GH) {
        const int p = py * GW + px;
        const float bg = 1.0f * (1.0f - A);   // BG = 1.0
#pragma unroll
        for (int c = 0; c < GC; c++)
            out[(size_t)c * GHW + p] = (acc[c] + bg) * s_tone[c];
        out[(size_t)GC * GHW + p] = D;              // depth image
        out[(size_t)GC * GHW + GHW + p] = A;        // A_final
    }
}

// ---------------------------------------------------------------------------
// Inputs (metadata order): positions[N,3], rotations[N,4](unused), scales[N,3],
// opacities[N], spectral_features[N,C], tone_mapping[C], intrinsics[3,3],
// extrinsics[4,4]. Output: concat(spectral[C,H,W], depth[H,W], A[H,W]) fp32.
// ---------------------------------------------------------------------------
extern "C" void kernel_launch(void* const* d_in, const int* in_sizes, int n_in,
                              void* d_out, int out_size)
{
    const float* positions  = (const float*)d_in[0];
    const float* scales     = (const float*)d_in[2];
    const float* opacities  = (const float*)d_in[3];
    const float* spectral   = (const float*)d_in[4];
    const float* tone       = (const float*)d_in[5];
    const float* intr       = (const float*)d_in[6];
    const float* extr       = (const float*)d_in[7];
    float* out = (float*)d_out;

    prep_kernel<<<1, GN>>>(positions, scales, opacities, intr, extr);

    dim3 grid((GW + TS - 1) / TS, (GH + TS - 1) / TS);
    render_kernel<<<grid, 256>>>(spectral, tone, out);
}

// round 4
// speedup vs baseline: 1.4816x; 1.4816x over previous
#include <cuda_runtime.h>
#include <cuda_bf16.h>
#include <stdint.h>

#define GN 512
#define GW 332
#define GH 324
#define GHW (GW * GH)
#define GC 120
#define TSX 16
#define TSY 4

__device__ float g_gx[GN], g_gy[GN], g_c00[GN], g_c11[GN], g_op[GN], g_dep[GN];
__device__ float g_rx[GN], g_ry[GN];
__device__ int   g_sid[GN];
__device__ int   g_cnt;

static __device__ __forceinline__ unsigned order_float(float f) {
    unsigned u = __float_as_uint(f);
    return (u & 0x80000000u) ? ~u : (u | 0x80000000u);
}

// ---------------------------------------------------------------------------
// Kernel 1: project, validity, cinv, stable sort by depth, compact valid set.
// One block, 512 threads (one per gaussian).
// ---------------------------------------------------------------------------
__global__ __launch_bounds__(GN) void prep_kernel(
    const float* __restrict__ pos,     // [N,3]
    const float* __restrict__ scales,  // [N,3]
    const float* __restrict__ ops,     // [N]
    const float* __restrict__ K,       // [3,3]
    const float* __restrict__ E)       // [4,4]
{
    __shared__ float s_gx[GN], s_gy[GN], s_c00[GN], s_c11[GN], s_op[GN], s_dep[GN];
    __shared__ unsigned char s_valid[GN];
    __shared__ unsigned long long s_key[GN];
    __shared__ int s_wcnt[16];

    const int i = threadIdx.x;

    float p0 = pos[3 * i + 0], p1 = pos[3 * i + 1], p2 = pos[3 * i + 2];
    // cam = E @ [p;1]
    float cx = E[0] * p0 + E[1] * p1 + E[2]  * p2 + E[3];
    float cy = E[4] * p0 + E[5] * p1 + E[6]  * p2 + E[7];
    float cz = E[8] * p0 + E[9] * p1 + E[10] * p2 + E[11];
    // proj = K @ cam3
    float prx = K[0] * cx + K[1] * cy + K[2] * cz;
    float pry = K[3] * cx + K[4] * cy + K[5] * cz;
    float prz = K[6] * cx + K[7] * cy + K[8] * cz;
    float sx = prx / (prz + 1e-6f);
    float sy = pry / (prz + 1e-6f);
    float d  = cz;

    bool valid = (d > 0.01f) && (d < 100.0f) &&
                 (sx > -100.0f) && (sx < (float)GW + 100.0f) &&
                 (sy > -100.0f) && (sy < (float)GH + 100.0f);

    float s0 = scales[3 * i + 0], s1 = scales[3 * i + 1];
    s_gx[i]  = sx;
    s_gy[i]  = sy;
    s_c00[i] = 1.0f / (s0 * s0 + 1e-4f);
    s_c11[i] = 1.0f / (s1 * s1 + 1e-4f);
    s_op[i]  = ops[i];
    s_dep[i] = d;
    s_valid[i] = valid ? 1 : 0;
    s_key[i] = ((unsigned long long)order_float(d) << 32) | (unsigned)i;
    __syncthreads();

    // Bitonic sort 512 keys ascending (depth, then index => stable argsort).
    for (int k = 2; k <= GN; k <<= 1) {
        for (int j = k >> 1; j > 0; j >>= 1) {
            __syncthreads();
            int ixj = i ^ j;
            if (ixj > i) {
                unsigned long long a = s_key[i], b = s_key[ixj];
                bool asc = ((i & k) == 0);
                if ((a > b) == asc) { s_key[i] = b; s_key[ixj] = a; }
            }
        }
    }
    __syncthreads();

    // Order-preserving compaction of valid entries.
    int src = (int)(s_key[i] & 0xffffffffu);
    bool keep = (s_valid[src] != 0);
    unsigned bm = __ballot_sync(0xffffffffu, keep);
    int lane = i & 31, w = i >> 5;
    if (lane == 0) s_wcnt[w] = __popc(bm);
    __syncthreads();
    int woff = 0;
#pragma unroll
    for (int ww = 0; ww < 16; ww++)
        if (ww < w) woff += s_wcnt[ww];
    if (keep) {
        int p = woff + __popc(bm & ((1u << lane) - 1u));
        float c00 = s_c00[src], c11 = s_c11[src];
        g_gx[p]  = s_gx[src];
        g_gy[p]  = s_gy[src];
        g_c00[p] = c00;
        g_c11[p] = c11;
        g_rx[p]  = sqrtf(36.0f / c00);   // 6-sigma radius
        g_ry[p]  = sqrtf(36.0f / c11);
        g_op[p]  = s_op[src];
        g_dep[p] = s_dep[src];
        g_sid[p] = src;
    }
    if (i == 0) {
        int tot = 0;
#pragma unroll
        for (int ww = 0; ww < 16; ww++) tot += s_wcnt[ww];
        g_cnt = tot;
    }
}

// ---------------------------------------------------------------------------
// Kernel 2: per-tile cull + per-pixel depth-ordered alpha compositing.
// Block = 256 threads = 64 pixels (16x4 tile) x 4 channel-groups.
// tid = cg*64 + pix  (warp-uniform cg -> warp-uniform spec loads & branches)
// Channel groups: [0,32) [32,64) [64,96) [96,120).
// ---------------------------------------------------------------------------
__global__ __launch_bounds__(256, 3) void render_kernel(
    const float* __restrict__ spec,   // [N, C]
    const float* __restrict__ tone,   // [C]
    float* __restrict__ out)          // [C*HW + HW + HW]
{
    __shared__ float t_gx[GN], t_gy[GN], t_c00[GN], t_c11[GN], t_op[GN], t_d[GN];
    __shared__ int   t_id[GN];
    __shared__ float s_tone[GC];
    __shared__ int   s_cnt, s_wcnt[8];

    const int tid = threadIdx.x;
    if (tid < GC) s_tone[tid] = tone[tid];
    if (tid == 0) s_cnt = 0;

    const int M  = g_cnt;
    const int x0 = blockIdx.x * TSX, y0 = blockIdx.y * TSY;
    const float fx0 = (float)x0, fx1 = (float)(x0 + TSX - 1);
    const float fy0 = (float)y0, fy1 = (float)(y0 + TSY - 1);
    const float CUT = 36.0f;   // 6-sigma: exp(-18) ~ 1.5e-8
    __syncthreads();

    // Order-preserving tile cull (chunks of 256).
    for (int base = 0; base < M; base += 256) {
        int i = base + tid;
        bool keep = false;
        if (i < M) {
            float gx = g_gx[i], gy = g_gy[i];
            float rx = g_rx[i], ry = g_ry[i];
            keep = (gx + rx >= fx0) && (gx - rx <= fx1) &&
                   (gy + ry >= fy0) && (gy - ry <= fy1);
        }
        unsigned bm = __ballot_sync(0xffffffffu, keep);
        int lane = tid & 31, w = tid >> 5;
        if (lane == 0) s_wcnt[w] = __popc(bm);
        __syncthreads();
        int woff = 0;
#pragma unroll
        for (int ww = 0; ww < 8; ww++)
            if (ww < w) woff += s_wcnt[ww];
        if (keep) {
            int p = s_cnt + woff + __popc(bm & ((1u << lane) - 1u));
            t_gx[p] = g_gx[i]; t_gy[p] = g_gy[i];
            t_c00[p] = g_c00[i]; t_c11[p] = g_c11[i];
            t_op[p] = g_op[i]; t_d[p] = g_dep[i]; t_id[p] = g_sid[i];
        }
        __syncthreads();
        if (tid == 0) {
            int tt = 0;
#pragma unroll
            for (int ww = 0; ww < 8; ww++) tt += s_wcnt[ww];
            s_cnt += tt;
        }
        __syncthreads();
    }
    const int cnt = s_cnt;

    const int cg  = tid >> 6;          // channel group 0..3 (warp-uniform)
    const int pix = tid & 63;          // pixel within 16x4 tile
    const int px  = x0 + (pix & 15);
    const int py  = y0 + (pix >> 4);
    const float fpx = (float)px, fpy = (float)py;
    const int cbase = cg * 32;         // 0,32,64,96

    float A = 0.0f, D = 0.0f;
    float acc[32];
#pragma unroll
    for (int c = 0; c < 32; c++) acc[c] = 0.0f;

    // Depth-ordered compositing over culled list (uniform LDS broadcasts).
    for (int k = 0; k < cnt; k++) {
        float dx = fpx - t_gx[k];
        float dy = fpy - t_gy[k];
        float m  = dx * dx * t_c00[k] + dy * dy * t_c11[k];
        float alpha = 0.0f;
        if (m < CUT) alpha = t_op[k] * __expf(-0.5f * m) * (1.0f - A);
        if (__any_sync(0xffffffffu, alpha != 0.0f)) {
            A += alpha;
            D += t_d[k] * alpha;
            const float4* sp = (const float4*)(spec + (size_t)t_id[k] * GC + cbase);
            if (cg < 3) {
#pragma unroll
                for (int q = 0; q < 8; q++) {
                    float4 v = __ldg(sp + q);
                    acc[4 * q + 0] += alpha * v.x;
                    acc[4 * q + 1] += alpha * v.y;
                    acc[4 * q + 2] += alpha * v.z;
                    acc[4 * q + 3] += alpha * v.w;
                }
            } else {
#pragma unroll
                for (int q = 0; q < 6; q++) {
                    float4 v = __ldg(sp + q);
                    acc[4 * q + 0] += alpha * v.x;
                    acc[4 * q + 1] += alpha * v.y;
                    acc[4 * q + 2] += alpha * v.z;
                    acc[4 * q + 3] += alpha * v.w;
                }
            }
        }
    }

    if (px < GW) {   // py always < GH (324 = 81*4)
        const int p = py * GW + px;
        const float bg = 1.0f - A;   // BG = 1.0
        const int nch = (cg < 3) ? 32 : 24;
#pragma unroll 8
        for (int c = 0; c < nch; c++)
            out[(size_t)(cbase + c) * GHW + p] = (acc[c] + bg) * s_tone[cbase + c];
        if (cg == 0) {
            out[(size_t)GC * GHW + p] = D;              // depth image
            out[(size_t)GC * GHW + GHW + p] = A;        // A_final
        }
    }
}

// ---------------------------------------------------------------------------
// Inputs (metadata order): positions[N,3], rotations[N,4](unused), scales[N,3],
// opacities[N], spectral_features[N,C], tone_mapping[C], intrinsics[3,3],
// extrinsics[4,4]. Output: concat(spectral[C,H,W], depth[H,W], A[H,W]) fp32.
// ---------------------------------------------------------------------------
extern "C" void kernel_launch(void* const* d_in, const int* in_sizes, int n_in,
                              void* d_out, int out_size)
{
    const float* positions  = (const float*)d_in[0];
    const float* scales     = (const float*)d_in[2];
    const float* opacities  = (const float*)d_in[3];
    const float* spectral   = (const float*)d_in[4];
    const float* tone       = (const float*)d_in[5];
    const float* intr       = (const float*)d_in[6];
    const float* extr       = (const float*)d_in[7];
    float* out = (float*)d_out;

    prep_kernel<<<1, GN>>>(positions, scales, opacities, intr, extr);

    dim3 grid((GW + TSX - 1) / TSX, (GH + TSY - 1) / TSY);
    render_kernel<<<grid, 256>>>(spectral, tone, out);
}